// round 3
// baseline (speedup 1.0000x reference)
#include <cuda_runtime.h>

#define NB 512
#define NA 32
#define ND 256
#define NN (NB*NA)          // 16384 nodes
#define NE 1048576          // edges
#define XO_ELEMS (NN*ND)    // 4194304
#define MASK_ELEMS (NB*NA*NA) // 524288

// ---------------- scratch (static device globals; no allocation) -------------
__device__ float g_Y[NN*ND];         // X @ W
__device__ float g_Xo_scratch[NN*ND];
__device__ float g_mask_scratch[MASK_ELEMS];
__device__ float g_dinv[NN];
__device__ int   g_deg[NN];
__device__ int   g_rowptr[NN+1];
__device__ int   g_cursor[NN];
__device__ int   g_src[NE];

// ---------------- helpers ----------------------------------------------------
__device__ __forceinline__ void fma4(float4& acc, float4 v, float c) {
    acc.x = fmaf(v.x, c, acc.x);
    acc.y = fmaf(v.y, c, acc.y);
    acc.z = fmaf(v.z, c, acc.z);
    acc.w = fmaf(v.w, c, acc.w);
}

// ---------------- K1: zero degree --------------------------------------------
__global__ void k_zero_deg() {
    int i = blockIdx.x * blockDim.x + threadIdx.x;
    if (i < NN) g_deg[i] = 0;
}

// ---------------- K2: degree histogram over targets --------------------------
__global__ void k_hist(const int* __restrict__ ei) {
    int e = blockIdx.x * blockDim.x + threadIdx.x;
    if (e < NE) {
        int t = ei[NE + e];
        atomicAdd(&g_deg[t], 1);
    }
}

// ---------------- K3: single-block scan + dinv + cursor init -----------------
// 1024 threads, 16 elements each (16384 total)
__global__ void k_scan() {
    __shared__ int sums[1024];
    int t = threadIdx.x;
    int base = t * 16;
    int local[16];
    int run = 0;
#pragma unroll
    for (int i = 0; i < 16; ++i) {
        int d = g_deg[base + i];
        local[i] = run;
        run += d;
        g_dinv[base + i] = rsqrtf((float)(d + 1));  // +1 self loop
    }
    sums[t] = run;
    __syncthreads();
    // Hillis-Steele inclusive scan over 1024 partials
    for (int off = 1; off < 1024; off <<= 1) {
        int v = (t >= off) ? sums[t - off] : 0;
        __syncthreads();
        sums[t] += v;
        __syncthreads();
    }
    int prev = (t == 0) ? 0 : sums[t - 1];
#pragma unroll
    for (int i = 0; i < 16; ++i) {
        int r = prev + local[i];
        g_rowptr[base + i] = r;
        g_cursor[base + i] = r;
    }
    if (t == 1023) g_rowptr[NN] = sums[1023];
}

// ---------------- K4: scatter edges into CSR ---------------------------------
__global__ void k_scatter(const int* __restrict__ ei) {
    int e = blockIdx.x * blockDim.x + threadIdx.x;
    if (e < NE) {
        int s = ei[e];
        int t = ei[NE + e];
        int pos = atomicAdd(&g_cursor[t], 1);
        g_src[pos] = s;
    }
}

// ---------------- K5: SGEMM  Y[N,256] = X[N,256] * W[256,256] -----------------
// block tile 64x64, 256 threads (16x16), 4x4 per thread, K-step 16
#define AS_STRIDE 68
__global__ void k_gemm(const float* __restrict__ X, const float* __restrict__ W) {
    __shared__ float As[16 * AS_STRIDE];   // As[k][m], padded
    __shared__ float Bs[16 * 64];          // Bs[k][n]

    int tid = threadIdx.x;
    int tx = tid & 15;
    int ty = tid >> 4;
    int m0 = blockIdx.x * 64;
    int n0 = blockIdx.y * 64;

    float acc[4][4];
#pragma unroll
    for (int i = 0; i < 4; ++i)
#pragma unroll
        for (int j = 0; j < 4; ++j) acc[i][j] = 0.0f;

    // load indices
    int am = tid >> 2;            // 0..63
    int ak = (tid & 3) * 4;       // 0,4,8,12
    int bk = tid >> 4;            // 0..15
    int bn = (tid & 15) * 4;      // 0..60

    for (int k0 = 0; k0 < 256; k0 += 16) {
        float4 av = *(const float4*)&X[(size_t)(m0 + am) * 256 + k0 + ak];
        float4 bv = *(const float4*)&W[(size_t)(k0 + bk) * 256 + n0 + bn];
        As[(ak + 0) * AS_STRIDE + am] = av.x;
        As[(ak + 1) * AS_STRIDE + am] = av.y;
        As[(ak + 2) * AS_STRIDE + am] = av.z;
        As[(ak + 3) * AS_STRIDE + am] = av.w;
        *(float4*)&Bs[bk * 64 + bn] = bv;
        __syncthreads();
#pragma unroll
        for (int kk = 0; kk < 16; ++kk) {
            float a0 = As[kk * AS_STRIDE + ty * 4 + 0];
            float a1 = As[kk * AS_STRIDE + ty * 4 + 1];
            float a2 = As[kk * AS_STRIDE + ty * 4 + 2];
            float a3 = As[kk * AS_STRIDE + ty * 4 + 3];
            float b0 = Bs[kk * 64 + tx * 4 + 0];
            float b1 = Bs[kk * 64 + tx * 4 + 1];
            float b2 = Bs[kk * 64 + tx * 4 + 2];
            float b3 = Bs[kk * 64 + tx * 4 + 3];
            acc[0][0] = fmaf(a0, b0, acc[0][0]); acc[0][1] = fmaf(a0, b1, acc[0][1]);
            acc[0][2] = fmaf(a0, b2, acc[0][2]); acc[0][3] = fmaf(a0, b3, acc[0][3]);
            acc[1][0] = fmaf(a1, b0, acc[1][0]); acc[1][1] = fmaf(a1, b1, acc[1][1]);
            acc[1][2] = fmaf(a1, b2, acc[1][2]); acc[1][3] = fmaf(a1, b3, acc[1][3]);
            acc[2][0] = fmaf(a2, b0, acc[2][0]); acc[2][1] = fmaf(a2, b1, acc[2][1]);
            acc[2][2] = fmaf(a2, b2, acc[2][2]); acc[2][3] = fmaf(a2, b3, acc[2][3]);
            acc[3][0] = fmaf(a3, b0, acc[3][0]); acc[3][1] = fmaf(a3, b1, acc[3][1]);
            acc[3][2] = fmaf(a3, b2, acc[3][2]); acc[3][3] = fmaf(a3, b3, acc[3][3]);
        }
        __syncthreads();
    }
#pragma unroll
    for (int i = 0; i < 4; ++i) {
        float4 v = make_float4(acc[i][0], acc[i][1], acc[i][2], acc[i][3]);
        *(float4*)&g_Y[(size_t)(m0 + ty * 4 + i) * 256 + n0 + tx * 4] = v;
    }
}

// ---------------- K6: gather aggregation (warp per target node) --------------
__global__ void k_aggregate(const float* __restrict__ bias, float* __restrict__ Xo) {
    int warp = (blockIdx.x * blockDim.x + threadIdx.x) >> 5;
    int lane = threadIdx.x & 31;
    if (warp >= NN) return;

    float din = g_dinv[warp];
    const float4* yself = (const float4*)&g_Y[(size_t)warp * 256];
    float cself = din * din;
    float4 acc0 = make_float4(0.f, 0.f, 0.f, 0.f);
    float4 acc1 = make_float4(0.f, 0.f, 0.f, 0.f);
    fma4(acc0, yself[lane], cself);
    fma4(acc1, yself[lane + 32], cself);

    int beg = g_rowptr[warp];
    int end = g_rowptr[warp + 1];
    int j = beg;
    for (; j + 1 < end; j += 2) {
        int s0 = g_src[j];
        int s1 = g_src[j + 1];
        float c0 = g_dinv[s0] * din;
        float c1 = g_dinv[s1] * din;
        const float4* y0 = (const float4*)&g_Y[(size_t)s0 * 256];
        const float4* y1 = (const float4*)&g_Y[(size_t)s1 * 256];
        float4 a0 = y0[lane], a1 = y0[lane + 32];
        float4 b0 = y1[lane], b1 = y1[lane + 32];
        fma4(acc0, a0, c0); fma4(acc1, a1, c0);
        fma4(acc0, b0, c1); fma4(acc1, b1, c1);
    }
    if (j < end) {
        int s0 = g_src[j];
        float c0 = g_dinv[s0] * din;
        const float4* y0 = (const float4*)&g_Y[(size_t)s0 * 256];
        fma4(acc0, y0[lane], c0);
        fma4(acc1, y0[lane + 32], c0);
    }

    // add bias
    float4 bv0 = *(const float4*)&bias[lane * 4];
    float4 bv1 = *(const float4*)&bias[128 + lane * 4];
    acc0.x += bv0.x; acc0.y += bv0.y; acc0.z += bv0.z; acc0.w += bv0.w;
    acc1.x += bv1.x; acc1.y += bv1.y; acc1.z += bv1.z; acc1.w += bv1.w;

    float4* orow = (float4*)&Xo[(size_t)warp * 256];
    orow[lane] = acc0;
    orow[lane + 32] = acc1;
}

// ---------------- K7: per-batch adjacency mask -------------------------------
// 1 block per batch, 1024 threads (32 warps, warp a = row a)
__global__ void k_adj(const float* __restrict__ Xo, float* __restrict__ mask) {
    __shared__ float xs[32 * 257];
    __shared__ float sqv[32];
    int b = blockIdx.x;
    int tid = threadIdx.x;
    int warp = tid >> 5;
    int lane = tid & 31;

    const float* xb = &Xo[(size_t)b * NA * ND];
    // load tile with padded stride 257
    for (int e = tid; e < NA * ND; e += 1024) {
        int r = e >> 8;
        int c = e & 255;
        xs[r * 257 + c] = xb[e];
    }
    __syncthreads();

    // sq[a] per warp
    {
        float s = 0.f;
#pragma unroll
        for (int k = lane; k < 256; k += 32) {
            float v = xs[warp * 257 + k];
            s = fmaf(v, v, s);
        }
#pragma unroll
        for (int off = 16; off > 0; off >>= 1)
            s += __shfl_xor_sync(0xFFFFFFFFu, s, off);
        if (lane == 0) sqv[warp] = s;
    }
    __syncthreads();

    // warp 'warp' computes row a = warp; lane = column c
    int a = warp, c = lane;
    float dot = 0.f;
    const float* xa = &xs[a * 257];
    const float* xc = &xs[c * 257];
#pragma unroll 8
    for (int k = 0; k < 256; ++k)
        dot = fmaf(xa[k], xc[k], dot);

    float score = sqv[a] + sqv[c] - 2.0f * dot;

    float mn = score, mx = score;
#pragma unroll
    for (int off = 16; off > 0; off >>= 1) {
        mn = fminf(mn, __shfl_xor_sync(0xFFFFFFFFu, mn, off));
        mx = fmaxf(mx, __shfl_xor_sync(0xFFFFFFFFu, mx, off));
    }
    float norm = (score - mn) / (mx - mn + 1e-5f);
    mask[(size_t)b * (NA * NA) + a * NA + c] = (norm > 0.5f) ? 1.0f : 0.0f;
}

// ---------------- launch ------------------------------------------------------
extern "C" void kernel_launch(void* const* d_in, const int* in_sizes, int n_in,
                              void* d_out, int out_size) {
    const float* X  = (const float*)d_in[0];
    const int*   ei = (const int*)d_in[1];
    const float* W  = (const float*)d_in[2];
    const float* bv = (const float*)d_in[3];
    float* out = (float*)d_out;

    // resolve output layout: tuple (Xo [N*D], mask [B*A*A]) flattened
    float* Xo;
    float* mask;
    if (out_size >= XO_ELEMS + MASK_ELEMS) {
        Xo = out;
        mask = out + XO_ELEMS;
    } else if (out_size >= XO_ELEMS) {
        Xo = out;
        float* dummy; cudaGetSymbolAddress((void**)&dummy, g_mask_scratch);
        mask = dummy;
    } else {
        float* dummy; cudaGetSymbolAddress((void**)&dummy, g_Xo_scratch);
        Xo = dummy;
        mask = out;
    }

    k_zero_deg<<<(NN + 255) / 256, 256>>>();
    k_hist<<<NE / 256, 256>>>(ei);
    k_scan<<<1, 1024>>>();
    k_scatter<<<NE / 256, 256>>>(ei);
    dim3 gg(NN / 64, 256 / 64);
    k_gemm<<<gg, 256>>>(X, W);
    k_aggregate<<<(NN * 32) / 256, 256>>>(bv, Xo);
    k_adj<<<NB, 1024>>>(Xo, mask);
}

// round 4
// speedup vs baseline: 1.0021x; 1.0021x over previous
#include <cuda_runtime.h>

#define NB 512
#define NA 32
#define ND 256
#define NN (NB*NA)          // 16384 nodes
#define NE 1048576          // edges
#define XO_ELEMS (NN*ND)    // 4194304
#define MASK_ELEMS (NB*NA*NA) // 524288

// ---------------- scratch (static device globals; no allocation) -------------
__device__ float g_Y[NN*ND];         // X @ W
__device__ float g_Xo_scratch[NN*ND];
__device__ float g_mask_scratch[MASK_ELEMS];
__device__ float g_dinv[NN];
__device__ int   g_deg[NN];
__device__ int   g_rowptr[NN+1];
__device__ int   g_cursor[NN];
__device__ int   g_src[NE];

// ---------------- helpers ----------------------------------------------------
__device__ __forceinline__ void fma4(float4& acc, float4 v, float c) {
    acc.x = fmaf(v.x, c, acc.x);
    acc.y = fmaf(v.y, c, acc.y);
    acc.z = fmaf(v.z, c, acc.z);
    acc.w = fmaf(v.w, c, acc.w);
}

// ---------------- K1: zero degree --------------------------------------------
__global__ void k_zero_deg() {
    int i = blockIdx.x * blockDim.x + threadIdx.x;
    if (i < NN) g_deg[i] = 0;
}

// ---------------- K2: degree histogram over targets --------------------------
__global__ void k_hist(const int* __restrict__ ei) {
    int e = blockIdx.x * blockDim.x + threadIdx.x;
    if (e < NE) {
        int t = ei[NE + e];
        atomicAdd(&g_deg[t], 1);
    }
}

// ---------------- K3: single-block scan + dinv + cursor init -----------------
// 1024 threads, 16 elements each (16384 total)
__global__ void k_scan() {
    __shared__ int sums[1024];
    int t = threadIdx.x;
    int base = t * 16;
    int local[16];
    int run = 0;
#pragma unroll
    for (int i = 0; i < 16; ++i) {
        int d = g_deg[base + i];
        local[i] = run;
        run += d;
        g_dinv[base + i] = rsqrtf((float)(d + 1));  // +1 self loop
    }
    sums[t] = run;
    __syncthreads();
    // Hillis-Steele inclusive scan over 1024 partials
    for (int off = 1; off < 1024; off <<= 1) {
        int v = (t >= off) ? sums[t - off] : 0;
        __syncthreads();
        sums[t] += v;
        __syncthreads();
    }
    int prev = (t == 0) ? 0 : sums[t - 1];
#pragma unroll
    for (int i = 0; i < 16; ++i) {
        int r = prev + local[i];
        g_rowptr[base + i] = r;
        g_cursor[base + i] = r;
    }
    if (t == 1023) g_rowptr[NN] = sums[1023];
}

// ---------------- K4: scatter edges into CSR ---------------------------------
__global__ void k_scatter(const int* __restrict__ ei) {
    int e = blockIdx.x * blockDim.x + threadIdx.x;
    if (e < NE) {
        int s = ei[e];
        int t = ei[NE + e];
        int pos = atomicAdd(&g_cursor[t], 1);
        g_src[pos] = s;
    }
}

// ---------------- K5: SGEMM  Y[N,256] = X[N,256] * W[256,256] -----------------
// block tile 64x64, 256 threads (16x16), 4x4 per thread, K-step 16
#define AS_STRIDE 68
__global__ void k_gemm(const float* __restrict__ X, const float* __restrict__ W) {
    __shared__ float As[16 * AS_STRIDE];   // As[k][m], padded
    __shared__ float Bs[16 * 64];          // Bs[k][n]

    int tid = threadIdx.x;
    int tx = tid & 15;
    int ty = tid >> 4;
    int m0 = blockIdx.x * 64;
    int n0 = blockIdx.y * 64;

    float acc[4][4];
#pragma unroll
    for (int i = 0; i < 4; ++i)
#pragma unroll
        for (int j = 0; j < 4; ++j) acc[i][j] = 0.0f;

    // load indices
    int am = tid >> 2;            // 0..63
    int ak = (tid & 3) * 4;       // 0,4,8,12
    int bk = tid >> 4;            // 0..15
    int bn = (tid & 15) * 4;      // 0..60

    for (int k0 = 0; k0 < 256; k0 += 16) {
        float4 av = *(const float4*)&X[(size_t)(m0 + am) * 256 + k0 + ak];
        float4 bv = *(const float4*)&W[(size_t)(k0 + bk) * 256 + n0 + bn];
        As[(ak + 0) * AS_STRIDE + am] = av.x;
        As[(ak + 1) * AS_STRIDE + am] = av.y;
        As[(ak + 2) * AS_STRIDE + am] = av.z;
        As[(ak + 3) * AS_STRIDE + am] = av.w;
        *(float4*)&Bs[bk * 64 + bn] = bv;
        __syncthreads();
#pragma unroll
        for (int kk = 0; kk < 16; ++kk) {
            float a0 = As[kk * AS_STRIDE + ty * 4 + 0];
            float a1 = As[kk * AS_STRIDE + ty * 4 + 1];
            float a2 = As[kk * AS_STRIDE + ty * 4 + 2];
            float a3 = As[kk * AS_STRIDE + ty * 4 + 3];
            float b0 = Bs[kk * 64 + tx * 4 + 0];
            float b1 = Bs[kk * 64 + tx * 4 + 1];
            float b2 = Bs[kk * 64 + tx * 4 + 2];
            float b3 = Bs[kk * 64 + tx * 4 + 3];
            acc[0][0] = fmaf(a0, b0, acc[0][0]); acc[0][1] = fmaf(a0, b1, acc[0][1]);
            acc[0][2] = fmaf(a0, b2, acc[0][2]); acc[0][3] = fmaf(a0, b3, acc[0][3]);
            acc[1][0] = fmaf(a1, b0, acc[1][0]); acc[1][1] = fmaf(a1, b1, acc[1][1]);
            acc[1][2] = fmaf(a1, b2, acc[1][2]); acc[1][3] = fmaf(a1, b3, acc[1][3]);
            acc[2][0] = fmaf(a2, b0, acc[2][0]); acc[2][1] = fmaf(a2, b1, acc[2][1]);
            acc[2][2] = fmaf(a2, b2, acc[2][2]); acc[2][3] = fmaf(a2, b3, acc[2][3]);
            acc[3][0] = fmaf(a3, b0, acc[3][0]); acc[3][1] = fmaf(a3, b1, acc[3][1]);
            acc[3][2] = fmaf(a3, b2, acc[3][2]); acc[3][3] = fmaf(a3, b3, acc[3][3]);
        }
        __syncthreads();
    }
#pragma unroll
    for (int i = 0; i < 4; ++i) {
        float4 v = make_float4(acc[i][0], acc[i][1], acc[i][2], acc[i][3]);
        *(float4*)&g_Y[(size_t)(m0 + ty * 4 + i) * 256 + n0 + tx * 4] = v;
    }
}

// ---------------- K6: gather aggregation (warp per target node) --------------
__global__ void k_aggregate(const float* __restrict__ bias, float* __restrict__ Xo) {
    int warp = (blockIdx.x * blockDim.x + threadIdx.x) >> 5;
    int lane = threadIdx.x & 31;
    if (warp >= NN) return;

    float din = g_dinv[warp];
    const float4* yself = (const float4*)&g_Y[(size_t)warp * 256];
    float cself = din * din;
    float4 acc0 = make_float4(0.f, 0.f, 0.f, 0.f);
    float4 acc1 = make_float4(0.f, 0.f, 0.f, 0.f);
    fma4(acc0, yself[lane], cself);
    fma4(acc1, yself[lane + 32], cself);

    int beg = g_rowptr[warp];
    int end = g_rowptr[warp + 1];
    int j = beg;
    for (; j + 1 < end; j += 2) {
        int s0 = g_src[j];
        int s1 = g_src[j + 1];
        float c0 = g_dinv[s0] * din;
        float c1 = g_dinv[s1] * din;
        const float4* y0 = (const float4*)&g_Y[(size_t)s0 * 256];
        const float4* y1 = (const float4*)&g_Y[(size_t)s1 * 256];
        float4 a0 = y0[lane], a1 = y0[lane + 32];
        float4 b0 = y1[lane], b1 = y1[lane + 32];
        fma4(acc0, a0, c0); fma4(acc1, a1, c0);
        fma4(acc0, b0, c1); fma4(acc1, b1, c1);
    }
    if (j < end) {
        int s0 = g_src[j];
        float c0 = g_dinv[s0] * din;
        const float4* y0 = (const float4*)&g_Y[(size_t)s0 * 256];
        fma4(acc0, y0[lane], c0);
        fma4(acc1, y0[lane + 32], c0);
    }

    // add bias
    float4 bv0 = *(const float4*)&bias[lane * 4];
    float4 bv1 = *(const float4*)&bias[128 + lane * 4];
    acc0.x += bv0.x; acc0.y += bv0.y; acc0.z += bv0.z; acc0.w += bv0.w;
    acc1.x += bv1.x; acc1.y += bv1.y; acc1.z += bv1.z; acc1.w += bv1.w;

    float4* orow = (float4*)&Xo[(size_t)warp * 256];
    orow[lane] = acc0;
    orow[lane + 32] = acc1;
}

// ---------------- K7: per-batch adjacency mask -------------------------------
// 1 block per batch, 1024 threads (32 warps, warp a = row a)
__global__ void k_adj(const float* __restrict__ Xo, float* __restrict__ mask) {
    __shared__ float xs[32 * 257];
    __shared__ float sqv[32];
    int b = blockIdx.x;
    int tid = threadIdx.x;
    int warp = tid >> 5;
    int lane = tid & 31;

    const float* xb = &Xo[(size_t)b * NA * ND];
    // load tile with padded stride 257
    for (int e = tid; e < NA * ND; e += 1024) {
        int r = e >> 8;
        int c = e & 255;
        xs[r * 257 + c] = xb[e];
    }
    __syncthreads();

    // sq[a] per warp
    {
        float s = 0.f;
#pragma unroll
        for (int k = lane; k < 256; k += 32) {
            float v = xs[warp * 257 + k];
            s = fmaf(v, v, s);
        }
#pragma unroll
        for (int off = 16; off > 0; off >>= 1)
            s += __shfl_xor_sync(0xFFFFFFFFu, s, off);
        if (lane == 0) sqv[warp] = s;
    }
    __syncthreads();

    // warp 'warp' computes row a = warp; lane = column c
    int a = warp, c = lane;
    float dot = 0.f;
    const float* xa = &xs[a * 257];
    const float* xc = &xs[c * 257];
#pragma unroll 8
    for (int k = 0; k < 256; ++k)
        dot = fmaf(xa[k], xc[k], dot);

    float score = sqv[a] + sqv[c] - 2.0f * dot;

    float mn = score, mx = score;
#pragma unroll
    for (int off = 16; off > 0; off >>= 1) {
        mn = fminf(mn, __shfl_xor_sync(0xFFFFFFFFu, mn, off));
        mx = fmaxf(mx, __shfl_xor_sync(0xFFFFFFFFu, mx, off));
    }
    float norm = (score - mn) / (mx - mn + 1e-5f);
    mask[(size_t)b * (NA * NA) + a * NA + c] = (norm > 0.5f) ? 1.0f : 0.0f;
}

// ---------------- launch ------------------------------------------------------
extern "C" void kernel_launch(void* const* d_in, const int* in_sizes, int n_in,
                              void* d_out, int out_size) {
    const float* X  = (const float*)d_in[0];
    const int*   ei = (const int*)d_in[1];
    const float* W  = (const float*)d_in[2];
    const float* bv = (const float*)d_in[3];
    float* out = (float*)d_out;

    // resolve output layout: tuple (Xo [N*D], mask [B*A*A]) flattened
    float* Xo;
    float* mask;
    if (out_size >= XO_ELEMS + MASK_ELEMS) {
        Xo = out;
        mask = out + XO_ELEMS;
    } else if (out_size >= XO_ELEMS) {
        Xo = out;
        float* dummy; cudaGetSymbolAddress((void**)&dummy, g_mask_scratch);
        mask = dummy;
    } else {
        float* dummy; cudaGetSymbolAddress((void**)&dummy, g_Xo_scratch);
        Xo = dummy;
        mask = out;
    }

    k_zero_deg<<<(NN + 255) / 256, 256>>>();
    k_hist<<<NE / 256, 256>>>(ei);
    k_scan<<<1, 1024>>>();
    k_scatter<<<NE / 256, 256>>>(ei);
    dim3 gg(NN / 64, 256 / 64);
    k_gemm<<<gg, 256>>>(X, W);
    k_aggregate<<<(NN * 32) / 256, 256>>>(bv, Xo);
    k_adj<<<NB, 1024>>>(Xo, mask);
}